// round 7
// baseline (speedup 1.0000x reference)
#include <cuda_runtime.h>
#include <cuda_fp16.h>
#include <cstdint>

// ---------------------------------------------------------------------------
// GNNEncoder: 2x (EdgeConv -> BatchNorm) + mean/max pooling
//
// Algebra: concat[x_i, x_j-x_i] @ Wa = x_i@(Wtop-Wbot) + x_j@Wbot
//   => per-node A[i], B[j]; per-edge layer-1 is A[dst]+B[src]
// BatchNorm folded into next node GEMM / pooling. Edges counting-sorted by
// dst => run-dedup atomicMax epilogue.
// R7: edge kernel at occupancy 2 (W fragments in SMEM, <=64 regs/thread,
//     __launch_bounds__(512,2)) so one CTA's MMA hides the other's
//     gather/convert/epilogue. Exact 3-term f16 split, all fp32 accum.
// ---------------------------------------------------------------------------

#define HC 64
#define NMAX 50000
#define EMAX 1600000
#define NEG_INF_BITS ((int)0xFF800000u)

typedef unsigned long long u64;

#define FMA2(d, a, b, c) \
    asm("fma.rn.f32x2 %0, %1, %2, %3;" : "=l"(d) : "l"(a), "l"(b), "l"(c))
#define PACK2(d, v) \
    asm("mov.b64 %0, {%1, %1};" : "=l"(d) : "r"(v))
#define UNPACK2(lo, hi, v) \
    asm("mov.b64 {%0, %1}, %2;" : "=r"(lo), "=r"(hi) : "l"(v))

// fp32-accumulator HMMA
#define MMA16816(c, a0, a1, a2, a3, b0, b1)                                  \
    asm volatile(                                                            \
        "mma.sync.aligned.m16n8k16.row.col.f32.f16.f16.f32 "                 \
        "{%0,%1,%2,%3}, {%4,%5,%6,%7}, {%8,%9}, {%0,%1,%2,%3};"              \
        : "+f"((c)[0]), "+f"((c)[1]), "+f"((c)[2]), "+f"((c)[3])             \
        : "r"(a0), "r"(a1), "r"(a2), "r"(a3), "r"(b0), "r"(b1))

__device__ __forceinline__ uint32_t pack_h2(__half lo, __half hi) {
    return (uint32_t)__half_as_ushort(lo) |
           ((uint32_t)__half_as_ushort(hi) << 16);
}

__device__ int   g_cnt[NMAX];
__device__ int   g_chunk[256];
__device__ int   g_src[EMAX];
__device__ int   g_dst[EMAX];
__device__ float g_A[NMAX * HC];
__device__ float g_B[NMAX * HC];
__device__ int   g_raw1[NMAX * HC];   // float bits, atomicMax as signed int
__device__ int   g_raw2[NMAX * HC];
__device__ float g_part[128 * 2 * HC];
__device__ float g_scale[2 * HC];
__device__ float g_shift[2 * HC];

// ---------------------------- small utilities ------------------------------

__global__ void k_zero_cnt(int n) {
    int i = blockIdx.x * blockDim.x + threadIdx.x;
    if (i < n) g_cnt[i] = 0;
}

__global__ void k_init_raw(int layer, int n) {
    int* raw = layer ? g_raw2 : g_raw1;
    for (int i = blockIdx.x * blockDim.x + threadIdx.x; i < n;
         i += gridDim.x * blockDim.x)
        raw[i] = NEG_INF_BITS;
}

__global__ void k_hist(const int* __restrict__ dst, int E) {
    for (int e = blockIdx.x * blockDim.x + threadIdx.x; e < E;
         e += gridDim.x * blockDim.x)
        atomicAdd(&g_cnt[dst[e]], 1);
}

__global__ void k_scan1(int n) {  // blockDim = 1024
    __shared__ int s[1024];
    int i = blockIdx.x * 1024 + threadIdx.x;
    int v = (i < n) ? g_cnt[i] : 0;
    s[threadIdx.x] = v;
    __syncthreads();
    for (int off = 1; off < 1024; off <<= 1) {
        int t = 0;
        if (threadIdx.x >= off) t = s[threadIdx.x - off];
        __syncthreads();
        s[threadIdx.x] += t;
        __syncthreads();
    }
    if (i < n) g_cnt[i] = s[threadIdx.x] - v;   // exclusive within chunk
    if (threadIdx.x == 1023) g_chunk[blockIdx.x] = s[1023];
}

__global__ void k_scan2(int nch) {
    if (threadIdx.x == 0 && blockIdx.x == 0) {
        int acc = 0;
        for (int i = 0; i < nch; i++) {
            int t = g_chunk[i];
            g_chunk[i] = acc;
            acc += t;
        }
    }
}

__global__ void k_scan3(int n) {
    int i = blockIdx.x * blockDim.x + threadIdx.x;
    if (i < n) g_cnt[i] += g_chunk[i >> 10];
}

__global__ void k_scatter(const int* __restrict__ src,
                          const int* __restrict__ dst, int E) {
    for (int e = blockIdx.x * blockDim.x + threadIdx.x; e < E;
         e += gridDim.x * blockDim.x) {
        int d = dst[e];
        int p = atomicAdd(&g_cnt[d], 1);
        g_src[p] = src[e];
        g_dst[p] = d;
    }
}

// ------------------------- per-node linear (A, B) ---------------------------

__global__ __launch_bounds__(256) void k_nodelin(
    const float* __restrict__ xin, int use_raw,
    const float* __restrict__ Wa,  // [128,64] row-major
    const float* __restrict__ ba, int n) {
    __shared__ float Ws[128 * 64];
    __shared__ float xs[32 * 65];
    int tid = threadIdx.x;
    for (int i = tid; i < 128 * 64; i += 256) Ws[i] = Wa[i];

    int row0 = blockIdx.x * 32;
    for (int i = tid; i < 32 * 64; i += 256) {
        int r = i >> 6, k = i & 63;
        int row = row0 + r;
        float v = 0.f;
        if (row < n) {
            if (use_raw)
                v = __int_as_float(g_raw1[row * 64 + k]) * g_scale[k] + g_shift[k];
            else
                v = xin[row * 64 + k];
        }
        xs[r * 65 + k] = v;
    }
    __syncthreads();

    int r = tid & 31, cg = tid >> 5;
    int c0 = cg * 8;
    u64 a2[4], b2[4];
#pragma unroll
    for (int j = 0; j < 4; j++) { a2[j] = 0ull; b2[j] = 0ull; }

#pragma unroll 8
    for (int k = 0; k < 64; k++) {
        float xv = xs[r * 65 + k];
        u64 xp;
        PACK2(xp, __float_as_uint(xv));
        ulonglong2 t0 = *(const ulonglong2*)&Ws[k * 64 + c0];
        ulonglong2 t1 = *(const ulonglong2*)&Ws[k * 64 + c0 + 4];
        ulonglong2 q0 = *(const ulonglong2*)&Ws[(64 + k) * 64 + c0];
        ulonglong2 q1 = *(const ulonglong2*)&Ws[(64 + k) * 64 + c0 + 4];
        FMA2(a2[0], xp, t0.x, a2[0]);
        FMA2(a2[1], xp, t0.y, a2[1]);
        FMA2(a2[2], xp, t1.x, a2[2]);
        FMA2(a2[3], xp, t1.y, a2[3]);
        FMA2(b2[0], xp, q0.x, b2[0]);
        FMA2(b2[1], xp, q0.y, b2[1]);
        FMA2(b2[2], xp, q1.x, b2[2]);
        FMA2(b2[3], xp, q1.y, b2[3]);
    }
    int row = row0 + r;
    if (row < n) {
        float a[8], b[8];
#pragma unroll
        for (int j = 0; j < 4; j++) {
            unsigned int lo, hi;
            UNPACK2(lo, hi, a2[j]);
            a[2 * j] = __uint_as_float(lo);
            a[2 * j + 1] = __uint_as_float(hi);
            UNPACK2(lo, hi, b2[j]);
            b[2 * j] = __uint_as_float(lo);
            b[2 * j + 1] = __uint_as_float(hi);
        }
#pragma unroll
        for (int j = 0; j < 8; j++) {
            float bb = ba[c0 + j];
            g_A[row * 64 + c0 + j] = a[j] - b[j] + bb;
            g_B[row * 64 + c0 + j] = b[j];
        }
    }
}

// ------------- edge kernel (mma.sync 3-term split, occupancy 2) -------------
// Per 128-edge tile:
//   gather t = relu(A[dst]+B[src]) -> split to f16 hi/lo -> SMEM tiles
//   C = th@Wh + th@Wl + tl@Wh  (all fp32 accum into one accumulator)
//   relu(C + bb) -> staging SMEM -> run-dedup atomicMax
// 512 threads = 16 warps: warp (eg 0..7, nh 0..1) = 16 edges x 32 cols.
// W fragments in SMEM (re-read per tile) to keep regs <= 64 for occupancy 2.

#define TILE_E 128
// dynamic smem (bytes)
#define SMO_DS   0                          // int [128]
#define SMO_SS   512                        // int [128]
#define SMO_WTH  1024                       // [64][33] u32, 8448 B
#define SMO_WTL  9472                       // 8448 B
#define SMO_AH   17920                      // [128][36] u32, 18432 B
#define SMO_AL   36352                      // 18432 B
#define SMO_STG  54784                      // [64][132] f32, 33792 B
#define SM_EDGE_TOTAL 88576

__device__ __forceinline__ void split16(float x, __half& h, __half& l) {
    h = __float2half_rn(x);
    l = __float2half_rn(x - __half2float(h));
}

__global__ __launch_bounds__(512, 2) void k_edge_mma(
    const float* __restrict__ Wb,   // [64k][64n]
    const float* __restrict__ bb,   // [64]
    int E, int layer) {
    extern __shared__ char sm[];
    int* ds = (int*)(sm + SMO_DS);
    int* ss = (int*)(sm + SMO_SS);
    uint32_t* WTH = (uint32_t*)(sm + SMO_WTH);
    uint32_t* WTL = (uint32_t*)(sm + SMO_WTL);
    uint32_t* AH = (uint32_t*)(sm + SMO_AH);
    uint32_t* AL = (uint32_t*)(sm + SMO_AL);
    float* STG = (float*)(sm + SMO_STG);

    int* out = layer ? g_raw2 : g_raw1;
    int tid = threadIdx.x;
    int wid = tid >> 5, lid = tid & 31;
    int gid = lid >> 2, tig = lid & 3;
    int eg = wid & 7, nh = wid >> 3;

    // ---- W split -> SMEM (transposed, half2-packed along k); persistent ----
    for (int i = tid; i < 64 * 32; i += 512) {
        int n = i >> 5, kp = i & 31;
        float w0 = Wb[(2 * kp) * 64 + n];
        float w1 = Wb[(2 * kp + 1) * 64 + n];
        __half h0, l0, h1, l1;
        split16(w0, h0, l0);
        split16(w1, h1, l1);
        WTH[n * 33 + kp] = pack_h2(h0, h1);
        WTL[n * 33 + kp] = pack_h2(l0, l1);
    }

    float bias[4][2];
#pragma unroll
    for (int nt = 0; nt < 4; nt++) {
        int c0 = nh * 32 + nt * 8 + tig * 2;
        bias[nt][0] = bb[c0];
        bias[nt][1] = bb[c0 + 1];
    }
    __syncthreads();

    int ntiles = (E + TILE_E - 1) / TILE_E;
    int ge = tid >> 2, gp = tid & 3;   // gather: 4 threads/edge, 16 k each

    for (int t = blockIdx.x; t < ntiles; t += gridDim.x) {
        int base = t * TILE_E;
        if (tid < TILE_E) {
            int e = base + tid;
            ds[tid] = (e < E) ? g_dst[e] : -1;
            ss[tid] = (e < E) ? g_src[e] : 0;
        }
        __syncthreads();

        // ---- gather + relu + f16 split -> AH/AL ----
        {
            int d = ds[ge], s = ss[ge];
            uint32_t* ah = AH + ge * 36 + gp * 8;
            uint32_t* al = AL + ge * 36 + gp * 8;
            if (d >= 0) {
                const float4* ap = (const float4*)&g_A[(size_t)d * 64 + gp * 16];
                const float4* bp = (const float4*)&g_B[(size_t)s * 64 + gp * 16];
#pragma unroll
                for (int q = 0; q < 4; q++) {
                    float4 av = ap[q], bv = bp[q];
                    float vx = fmaxf(av.x + bv.x, 0.f);
                    float vy = fmaxf(av.y + bv.y, 0.f);
                    float vz = fmaxf(av.z + bv.z, 0.f);
                    float vw = fmaxf(av.w + bv.w, 0.f);
                    __half hx, lx, hy, ly, hz, lz, hw, lw;
                    split16(vx, hx, lx);
                    split16(vy, hy, ly);
                    split16(vz, hz, lz);
                    split16(vw, hw, lw);
                    ((uint2*)ah)[q] = make_uint2(pack_h2(hx, hy), pack_h2(hz, hw));
                    ((uint2*)al)[q] = make_uint2(pack_h2(lx, ly), pack_h2(lz, lw));
                }
            } else {
#pragma unroll
                for (int q = 0; q < 4; q++) {
                    ((uint2*)ah)[q] = make_uint2(0u, 0u);
                    ((uint2*)al)[q] = make_uint2(0u, 0u);
                }
            }
        }
        __syncthreads();

        // ---- tensor GEMM: 4 kt x 4 nt x 3 terms, single fp32 accumulator ----
        float acc[4][4];
#pragma unroll
        for (int nt = 0; nt < 4; nt++)
#pragma unroll
            for (int j = 0; j < 4; j++) acc[nt][j] = 0.f;

        int erow = eg * 16 + gid;
#pragma unroll
        for (int kt = 0; kt < 4; kt++) {
            int kp = kt * 8 + tig;
            uint32_t ah0 = AH[erow * 36 + kp];
            uint32_t ah1 = AH[(erow + 8) * 36 + kp];
            uint32_t ah2 = AH[erow * 36 + kp + 4];
            uint32_t ah3 = AH[(erow + 8) * 36 + kp + 4];
            uint32_t al0 = AL[erow * 36 + kp];
            uint32_t al1 = AL[(erow + 8) * 36 + kp];
            uint32_t al2 = AL[erow * 36 + kp + 4];
            uint32_t al3 = AL[(erow + 8) * 36 + kp + 4];
#pragma unroll
            for (int nt = 0; nt < 4; nt++) {
                int n = nh * 32 + nt * 8 + gid;
                uint32_t wh0 = WTH[n * 33 + kp];
                uint32_t wh1 = WTH[n * 33 + kp + 4];
                uint32_t wl0 = WTL[n * 33 + kp];
                uint32_t wl1 = WTL[n * 33 + kp + 4];
                MMA16816(acc[nt], ah0, ah1, ah2, ah3, wh0, wh1);
                MMA16816(acc[nt], ah0, ah1, ah2, ah3, wl0, wl1);
                MMA16816(acc[nt], al0, al1, al2, al3, wh0, wh1);
            }
        }

        // ---- bias + relu -> staging [col][edge] stride 132 ----
#pragma unroll
        for (int nt = 0; nt < 4; nt++) {
            int c0 = nh * 32 + nt * 8 + tig * 2;
            STG[c0 * 132 + erow]           = fmaxf(acc[nt][0] + bias[nt][0], 0.f);
            STG[(c0 + 1) * 132 + erow]     = fmaxf(acc[nt][1] + bias[nt][1], 0.f);
            STG[c0 * 132 + erow + 8]       = fmaxf(acc[nt][2] + bias[nt][0], 0.f);
            STG[(c0 + 1) * 132 + erow + 8] = fmaxf(acc[nt][3] + bias[nt][1], 0.f);
        }
        __syncthreads();

        // ---- run-dedup atomicMax (edges sorted by dst) ----
        {
            int c = tid >> 3;
            int seg = (tid & 7) * 16;
            const float* sp = STG + c * 132 + seg;
            float v[16];
#pragma unroll
            for (int q = 0; q < 4; q++) {
                float4 f = *(const float4*)(sp + q * 4);
                v[q * 4 + 0] = f.x; v[q * 4 + 1] = f.y;
                v[q * 4 + 2] = f.z; v[q * 4 + 3] = f.w;
            }
            int d = ds[seg];
            float m = v[0];
#pragma unroll
            for (int i = 1; i < 16; i++) {
                int dn = ds[seg + i];
                if (dn == d) {
                    m = fmaxf(m, v[i]);
                } else {
                    if (d >= 0) atomicMax(&out[d * 64 + c], __float_as_int(m));
                    d = dn;
                    m = v[i];
                }
            }
            if (d >= 0) atomicMax(&out[d * 64 + c], __float_as_int(m));
        }
        __syncthreads();   // ds/ss + AH/AL + STG free for next tile
    }
}

// ------------------------------ batchnorm ----------------------------------

__global__ void k_bnstats(int layer, int n) {  // grid 128, block 256
    const int* raw = layer ? g_raw2 : g_raw1;
    int tid = threadIdx.x;
    int c = tid & 63, gq = tid >> 6;
    float s = 0.f, s2 = 0.f;
    for (int r = blockIdx.x * 4 + gq; r < n; r += 512) {
        float v = __int_as_float(raw[r * 64 + c]);
        s += v;
        s2 += v * v;
    }
    __shared__ float sh[256], sh2[256];
    sh[tid] = s;
    sh2[tid] = s2;
    __syncthreads();
    if (gq == 0) {
#pragma unroll
        for (int q = 1; q < 4; q++) {
            s += sh[q * 64 + c];
            s2 += sh2[q * 64 + c];
        }
        g_part[blockIdx.x * 128 + c] = s;
        g_part[blockIdx.x * 128 + 64 + c] = s2;
    }
}

__global__ void k_bnfinal(const float* __restrict__ gamma,
                          const float* __restrict__ beta, int n, int layer) {
    int c = threadIdx.x;
    if (c < 64) {
        float s = 0.f, s2 = 0.f;
        for (int b = 0; b < 128; b++) {
            s += g_part[b * 128 + c];
            s2 += g_part[b * 128 + 64 + c];
        }
        float mean = s / (float)n;
        float var = s2 / (float)n - mean * mean;
        float sc = gamma[c] * rsqrtf(var + 1e-5f);
        g_scale[layer * 64 + c] = sc;
        g_shift[layer * 64 + c] = beta[c] - mean * sc;
    }
}

// ---------------------- pooling + BN2 finalize + h write --------------------

__global__ __launch_bounds__(256) void k_pool(
    const int* __restrict__ batch, int n, int G,
    float* __restrict__ outh, float* __restrict__ outg) {
    int g = blockIdx.x;
    int lo = 0, hi = n;
    while (lo < hi) {
        int mid = (lo + hi) >> 1;
        if (batch[mid] < g) lo = mid + 1; else hi = mid;
    }
    int start = lo;
    hi = n;
    while (lo < hi) {
        int mid = (lo + hi) >> 1;
        if (batch[mid] < g + 1) lo = mid + 1; else hi = mid;
    }
    int end = lo;

    int tid = threadIdx.x;
    int c = tid & 63, gq = tid >> 6;
    float sc = g_scale[64 + c], sh = g_shift[64 + c];
    float s = 0.f, m = __int_as_float(NEG_INF_BITS);
    for (int r = start + gq; r < end; r += 4) {
        float v = __int_as_float(g_raw2[r * 64 + c]) * sc + sh;
        outh[(size_t)r * 64 + c] = v;
        s += v;
        m = fmaxf(m, v);
    }
    __shared__ float shs[256], shm[256];
    shs[tid] = s;
    shm[tid] = m;
    __syncthreads();
    if (gq == 0) {
#pragma unroll
        for (int q = 1; q < 4; q++) {
            s += shs[q * 64 + c];
            m = fmaxf(m, shm[q * 64 + c]);
        }
        int cnt = end - start;
        float mean = s / fmaxf((float)cnt, 1.f);
        float mx = (cnt > 0) ? m : __int_as_float(NEG_INF_BITS);
        outg[g * 128 + c] = mean;
        outg[g * 128 + 64 + c] = mx;
    }
}

// ------------------------------- launch ------------------------------------

extern "C" void kernel_launch(void* const* d_in, const int* in_sizes, int n_in,
                              void* d_out, int out_size) {
    const float* x    = (const float*)d_in[0];
    const int*   ei   = (const int*)d_in[1];
    const int*   batch = (const int*)d_in[2];
    const float* W1a = (const float*)d_in[3];
    const float* b1a = (const float*)d_in[4];
    const float* W1b = (const float*)d_in[5];
    const float* b1b = (const float*)d_in[6];
    const float* g1  = (const float*)d_in[7];
    const float* be1 = (const float*)d_in[8];
    const float* W2a = (const float*)d_in[9];
    const float* b2a = (const float*)d_in[10];
    const float* W2b = (const float*)d_in[11];
    const float* b2b = (const float*)d_in[12];
    const float* g2  = (const float*)d_in[13];
    const float* be2 = (const float*)d_in[14];

    int N = in_sizes[0] / 64;
    int E = in_sizes[1] / 2;
    int G = (out_size - N * 64) / 128;
    const int* src = ei;
    const int* dst = ei + E;

    float* outh = (float*)d_out;
    float* outg = outh + (size_t)N * 64;

    cudaFuncSetAttribute(k_edge_mma,
                         cudaFuncAttributeMaxDynamicSharedMemorySize,
                         SM_EDGE_TOTAL);

    // --- counting sort of edges by dst ---
    k_zero_cnt<<<(N + 255) / 256, 256>>>(N);
    k_hist<<<1024, 256>>>(dst, E);
    int nch = (N + 1023) / 1024;
    k_scan1<<<nch, 1024>>>(N);
    k_scan2<<<1, 32>>>(nch);
    k_scan3<<<(N + 255) / 256, 256>>>(N);
    k_scatter<<<1024, 256>>>(src, dst, E);

    // --- layer 1 ---
    k_nodelin<<<(N + 31) / 32, 256>>>(x, 0, W1a, b1a, N);
    k_init_raw<<<2048, 256>>>(0, N * 64);
    k_edge_mma<<<304, 512, SM_EDGE_TOTAL>>>(W1b, b1b, E, 0);
    k_bnstats<<<128, 256>>>(0, N);
    k_bnfinal<<<1, 64>>>(g1, be1, N, 0);

    // --- layer 2 (BN1 folded into the node linear via g_scale/g_shift) ---
    k_nodelin<<<(N + 31) / 32, 256>>>(nullptr, 1, W2a, b2a, N);
    k_init_raw<<<2048, 256>>>(1, N * 64);
    k_edge_mma<<<304, 512, SM_EDGE_TOTAL>>>(W2b, b2b, E, 1);
    k_bnstats<<<128, 256>>>(1, N);
    k_bnfinal<<<1, 64>>>(g2, be2, N, 1);

    // --- BN2 finalize + h write + mean/max pooling ---
    k_pool<<<G, 256>>>(batch, N, G, outh, outg);
}